// round 14
// baseline (speedup 1.0000x reference)
#include <cuda_runtime.h>
#include <cuda_bf16.h>
#include <math.h>

#define BB 2
#define NN 2048
#define TT 256
#define DD 128
#define KK 16
#define NTOT (BB*NN)

typedef unsigned long long ull;
typedef unsigned int u32;

// ---------------- scalar f32x2 helpers ----------------
__device__ __forceinline__ ull ffma2(ull a, ull b, ull c){
    ull d; asm("fma.rn.f32x2 %0, %1, %2, %3;" : "=l"(d) : "l"(a), "l"(b), "l"(c));
    return d;
}
__device__ __forceinline__ float usum(ull v){
    float lo, hi; asm("mov.b64 {%0,%1}, %2;" : "=f"(lo), "=f"(hi) : "l"(v));
    return lo + hi;
}
__device__ __forceinline__ float ulo(ull v){
    float lo, hi; asm("mov.b64 {%0,%1}, %2;" : "=f"(lo), "=f"(hi) : "l"(v));
    return lo;
}
__device__ __forceinline__ float uhi(ull v){
    float lo, hi; asm("mov.b64 {%0,%1}, %2;" : "=f"(lo), "=f"(hi) : "l"(v));
    return hi;
}
__device__ __forceinline__ ull pk(float lo, float hi){
    ull r; asm("mov.b64 %0, {%1,%2};" : "=l"(r) : "f"(lo), "f"(hi));
    return r;
}

// ---------------- mma helpers ----------------
__device__ __forceinline__ u32 smaddr(const void* p){
    return (u32)__cvta_generic_to_shared(p);
}
__device__ __forceinline__ void ldsm4(u32 &r0,u32 &r1,u32 &r2,u32 &r3, u32 a){
    asm volatile("ldmatrix.sync.aligned.m8n8.x4.shared.b16 {%0,%1,%2,%3}, [%4];"
                 : "=r"(r0),"=r"(r1),"=r"(r2),"=r"(r3) : "r"(a));
}
__device__ __forceinline__ void mma_bf16(float* c, const u32* a, u32 b0, u32 b1){
    asm volatile("mma.sync.aligned.m16n8k16.row.col.f32.bf16.bf16.f32 "
        "{%0,%1,%2,%3},{%4,%5,%6,%7},{%8,%9},{%0,%1,%2,%3};"
        : "+f"(c[0]),"+f"(c[1]),"+f"(c[2]),"+f"(c[3])
        : "r"(a[0]),"r"(a[1]),"r"(a[2]),"r"(a[3]),"r"(b0),"r"(b1));
}
__device__ __forceinline__ u32 a_addr(u32 base, int row0, int k0, int lane, int sB){
    int g = lane >> 3, r = lane & 7;
    return base + (u32)((row0 + r + (g & 1)*8)*sB + (k0 + (g >> 1)*8)*2);
}
__device__ __forceinline__ void split_bf(float x, __nv_bfloat16 &h, __nv_bfloat16 &l){
    h = __float2bfloat16(x);
    l = __float2bfloat16(x - __bfloat162float(h));
}
__device__ __forceinline__ u32 bfpack(__nv_bfloat16 a, __nv_bfloat16 b){
    __nv_bfloat162 t; t.x = a; t.y = b; return *(u32*)&t;
}

// ---------------- scratch ----------------
__device__ float g_u   [NTOT*DD];
__device__ float g_u2  [NTOT*DD];
__device__ float g_base[NTOT*DD];
__device__ float g_proj[NTOT*DD];
__device__ float g_loc [NTOT*DD];
__device__ int   g_idx [NTOT*KK];
__device__ ull   g_skey[NTOT];
__device__ int   g_pos [NTOT];
__device__ __align__(16) ull g_wpack[64*128];                // fc_w k-pair pack
__device__ __align__(16) uint4 g_wfrag[14*4096];             // mma B-fragment packs
__device__ __align__(16) __nv_bfloat16 g_spl[6*NTOT*DD];     // vh,vl,wh,wl,uh,ul

// ---------------- Kernel 0: merged weight packs -------------------------------
struct WF { const float* p[15]; };
__global__ void __launch_bounds__(128) k_pack(WF wf, uint4* __restrict__ dst,
                                              float2* __restrict__ fcdst){
    int m = blockIdx.y;
    if (m == 14) {
        const float* W = wf.p[14];
        int i = blockIdx.x*128 + threadIdx.x;
        int kp = i >> 7, c = i & 127;
        fcdst[i] = make_float2(W[(2*kp)*DD + c], W[(2*kp+1)*DD + c]);
        return;
    }
    if (blockIdx.x >= 32) return;
    const float* W = wf.p[m];
    int l = threadIdx.x & 31;
    int pair = blockIdx.x*4 + (threadIdx.x >> 5);
    int c = pair >> 3, s = pair & 7;
    int kk = s*16 + 2*(l & 3);
    int nn = c*8 + (l >> 2);
    float w00 = W[(size_t)kk*DD + nn],     w01 = W[(size_t)(kk+1)*DD + nn];
    float w10 = W[(size_t)(kk+8)*DD + nn], w11 = W[(size_t)(kk+9)*DD + nn];
    __nv_bfloat16 h00,h01,h10,h11,l00,l01,l10,l11;
    split_bf(w00,h00,l00); split_bf(w01,h01,l01);
    split_bf(w10,h10,l10); split_bf(w11,h11,l11);
    uint4 q;
    q.x = bfpack(h00,h01); q.y = bfpack(h10,h11);
    q.z = bfpack(l00,l01); q.w = bfpack(l10,l11);
    dst[(size_t)m*4096 + pair*32 + l] = q;
}

// ---------------- Kernel 1: TemporalLift — channel-pair f32x2 ----------------
__global__ void __launch_bounds__(128) k_lift(
    const float* __restrict__ spikes, const float* __restrict__ conv_w,
    const float* __restrict__ conv_b, const ull* __restrict__ fcp,
    const float* __restrict__ fc_b, float* __restrict__ u)
{
    __shared__ __align__(16) ull sp2[2][TT+8];
    __shared__ __align__(16) float xm[2][DD];
    __shared__ float warpsum[4];
    int node0 = blockIdx.x*2;
    int tid = threadIdx.x;
    int nd = tid >> 6;
    int q  = tid & 63;

    const float* s = spikes + (size_t)(node0+nd)*TT;
    float v0 = s[q], v1 = s[q+64], v2 = s[q+128], v3 = s[q+192];
    sp2[nd][2+q]      = pk(v0,v0);
    sp2[nd][2+q+64]   = pk(v1,v1);
    sp2[nd][2+q+128]  = pk(v2,v2);
    sp2[nd][2+q+192]  = pk(v3,v3);
    if (q < 2) sp2[nd][q] = 0ull;
    if (q < 6) sp2[nd][TT+2+q] = 0ull;

    float part = v0 + v1 + v2 + v3;
    #pragma unroll
    for (int sft = 16; sft > 0; sft >>= 1)
        part += __shfl_xor_sync(0xffffffffu, part, sft);
    if ((tid & 31) == 0) warpsum[tid >> 5] = part;
    __syncthreads();
    float S = warpsum[2*nd] + warpsum[2*nd+1];

    int c0 = q, c1 = q + 64;
    float w0a = conv_w[c0*5+0], w1a = conv_w[c0*5+1], w2a = conv_w[c0*5+2],
          w3a = conv_w[c0*5+3], w4a = conv_w[c0*5+4];
    float w0b = conv_w[c1*5+0], w1b = conv_w[c1*5+1], w2b = conv_w[c1*5+2],
          w3b = conv_w[c1*5+3], w4b = conv_w[c1*5+4];
    float bba = conv_b[c0], bbb = conv_b[c1];
    ull w0p = pk(w0a,w0b), w1p = pk(w1a,w1b), w2p = pk(w2a,w2b),
        w3p = pk(w3a,w3b), w4p = pk(w4a,w4b), bbp = pk(bba,bbb);
    const ull ONE2 = 0x3f8000003f800000ULL;
    const ull MASK = 0x7fffffff7fffffffULL;

    ull acc2 = 0ull;
    ulonglong2 A = *(const ulonglong2*)&sp2[nd][0];
    ulonglong2 B = *(const ulonglong2*)&sp2[nd][2];
    #pragma unroll 8
    for (int x = 0; x < 256; x += 4) {
        ulonglong2 Cq = *(const ulonglong2*)&sp2[nd][x+4];
        ulonglong2 Dq = *(const ulonglong2*)&sp2[nd][x+6];
        ull d0 = A.x, d1 = A.y, d2 = B.x, d3 = B.y;
        ull d4 = Cq.x, d5 = Cq.y, d6 = Dq.x, d7 = Dq.y;
        ull o0 = ffma2(w4p,d4, ffma2(w3p,d3, ffma2(w2p,d2, ffma2(w1p,d1, ffma2(w0p,d0, bbp)))));
        ull o1 = ffma2(w4p,d5, ffma2(w3p,d4, ffma2(w2p,d3, ffma2(w1p,d2, ffma2(w0p,d1, bbp)))));
        ull o2 = ffma2(w4p,d6, ffma2(w3p,d5, ffma2(w2p,d4, ffma2(w1p,d3, ffma2(w0p,d2, bbp)))));
        ull o3 = ffma2(w4p,d7, ffma2(w3p,d6, ffma2(w2p,d5, ffma2(w1p,d4, ffma2(w0p,d3, bbp)))));
        acc2 = ffma2(o0 & MASK, ONE2, acc2);
        acc2 = ffma2(o1 & MASK, ONE2, acc2);
        acc2 = ffma2(o2 & MASK, ONE2, acc2);
        acc2 = ffma2(o3 & MASK, ONE2, acc2);
        A = Cq; B = Dq;
    }
    float sa = ulo(acc2), sb = uhi(acc2);
    float s0 = ulo(sp2[nd][2]),   s1 = ulo(sp2[nd][3]);
    float s254 = ulo(sp2[nd][256]), s255 = ulo(sp2[nd][257]);
    float lina = 256.f*bba
               + w0a*(S - s254 - s255) + w1a*(S - s255) + w2a*S
               + w3a*(S - s0) + w4a*(S - s0 - s1);
    float linb = 256.f*bbb
               + w0b*(S - s254 - s255) + w1b*(S - s255) + w2b*S
               + w3b*(S - s0) + w4b*(S - s0 - s1);
    xm[nd][c0] = (lina + sa) * (0.5f/256.f);
    xm[nd][c1] = (linb + sb) * (0.5f/256.f);
    __syncthreads();

    int h = tid;
    ull oa = 0ull, ob = 0ull;
    #pragma unroll 8
    for (int kp = 0; kp < 64; kp++) {
        ull wv = __ldg(&fcp[kp*DD + h]);
        oa = ffma2(*(const ull*)&xm[0][2*kp], wv, oa);
        ob = ffma2(*(const ull*)&xm[1][2*kp], wv, ob);
    }
    float fb = fc_b[h];
    u[(size_t)node0*DD + h]     = fmaxf(usum(oa) + fb, 0.f);
    u[(size_t)(node0+1)*DD + h] = fmaxf(usum(ob) + fb, 0.f);
}

// ---------------- Kernel 2a: rank-by-counting ---------------------------------
__global__ void __launch_bounds__(256) k_rank(
    const float* __restrict__ coords, ull* __restrict__ skey, int* __restrict__ pos)
{
    __shared__ float c[NN];
    int b = blockIdx.y;
    const float* cb = coords + (size_t)b*NN;
    for (int j = threadIdx.x; j < NN; j += 256) c[j] = cb[j];
    __syncthreads();
    int w = threadIdx.x >> 5, l = threadIdx.x & 31;
    int i = blockIdx.x*8 + w;
    float ci = c[i];
    u32 cib = __float_as_uint(ci);
    int cnt = 0;
    #pragma unroll 4
    for (int t = 0; t < NN/32; t++) {
        int j = t*32 + l;
        u32 cjb = __float_as_uint(c[j]);
        cnt += (cjb < cib) || (cjb == cib && j < i);
    }
    #pragma unroll
    for (int s = 16; s > 0; s >>= 1)
        cnt += __shfl_xor_sync(0xffffffffu, cnt, s);
    if (l == 0) {
        skey[(size_t)b*NN + cnt] = ((ull)cib << 32) | (u32)i;
        pos[(size_t)b*NN + i] = cnt;
    }
}

// ---------------- Kernel 2b: kNN via two-pointer window (128-thr blocks) -----
__global__ void __launch_bounds__(128) k_knn2(
    const ull* __restrict__ skey, const int* __restrict__ pos, int* __restrict__ idx)
{
    __shared__ ull sk[NN];
    int b = blockIdx.y;
    for (int i = threadIdx.x; i < NN; i += 128) sk[i] = skey[(size_t)b*NN + i];
    __syncthreads();
    int i = blockIdx.x*128 + threadIdx.x;
    int p = pos[(size_t)b*NN + i];
    float ci = __uint_as_float((u32)(sk[p] >> 32));
    int lo = p, hi = p + 1;
    int* o = idx + ((size_t)b*NN + i)*KK;
    #pragma unroll
    for (int r = 0; r < KK; r++) {
        ull cl = ~0ull, ch = ~0ull;
        if (lo >= 0) {
            ull v = sk[lo];
            float d = __uint_as_float((u32)(v >> 32)) - ci;
            cl = ((ull)__float_as_uint(d*d) << 32) | (v & 0xffffffffull);
        }
        if (hi < NN) {
            ull v = sk[hi];
            float d = __uint_as_float((u32)(v >> 32)) - ci;
            ch = ((ull)__float_as_uint(d*d) << 32) | (v & 0xffffffffull);
        }
        if (cl <= ch) { o[r] = (int)(cl & 0xffffffffull); lo--; }
        else          { o[r] = (int)(ch & 0xffffffffull); hi++; }
    }
}

// ---------------- Kernel 3: node GEMMs via tensor cores (32-row tiles) -------
template<int NMAT, bool EX, bool OUTBF>
__global__ void __launch_bounds__(256) k_node_mma(
    const float* __restrict__ X,
    const uint4* __restrict__ F0, const uint4* __restrict__ F1,
    const uint4* __restrict__ F2,
    const float* __restrict__ cb0, const float* __restrict__ cb2,
    const float* __restrict__ rv0, const float* __restrict__ rv1,
    const float* __restrict__ xs,
    float* __restrict__ Y0, float* __restrict__ Y1, float* __restrict__ Y2,
    __nv_bfloat16* __restrict__ spl)
{
    __shared__ __align__(16) __nv_bfloat16 sAh[32*136];
    __shared__ __align__(16) __nv_bfloat16 sAl[32*136];
    __shared__ float xc[32];
    int tid = threadIdx.x;
    int row0 = blockIdx.x*32;

    #pragma unroll
    for (int it = 0; it < 4; it++) {
        int idx = tid + it*256;
        int r = idx >> 5, q = idx & 31;
        float4 v = *(const float4*)(X + (size_t)(row0+r)*DD + q*4);
        __nv_bfloat16 h0,h1,h2,h3,l0,l1,l2,l3;
        split_bf(v.x,h0,l0); split_bf(v.y,h1,l1);
        split_bf(v.z,h2,l2); split_bf(v.w,h3,l3);
        u32 ph0 = bfpack(h0,h1), ph1 = bfpack(h2,h3);
        u32 pl0 = bfpack(l0,l1), pl1 = bfpack(l2,l3);
        *(u32*)&sAh[r*136 + q*4]     = ph0;
        *(u32*)&sAh[r*136 + q*4 + 2] = ph1;
        *(u32*)&sAl[r*136 + q*4]     = pl0;
        *(u32*)&sAl[r*136 + q*4 + 2] = pl1;
        if (OUTBF) {
            size_t o = (size_t)(row0+r)*DD + q*4;
            *(u32*)(spl + (size_t)4*NTOT*DD + o)     = ph0;
            *(u32*)(spl + (size_t)4*NTOT*DD + o + 2) = ph1;
            *(u32*)(spl + (size_t)5*NTOT*DD + o)     = pl0;
            *(u32*)(spl + (size_t)5*NTOT*DD + o + 2) = pl1;
        }
    }
    if (EX && tid < 32) xc[tid] = xs[row0 + tid];
    __syncthreads();

    int l = tid & 31, w = tid >> 5;
    int mg = w >> 2, nh = w & 3;
    int rw = mg*16;
    const uint4* Fs[3] = {F0, F1, (NMAT > 2) ? F2 : F0};
    float C[NMAT][4][4];
    #pragma unroll
    for (int m = 0; m < NMAT; m++)
        #pragma unroll
        for (int cc = 0; cc < 4; cc++)
            #pragma unroll
            for (int t = 0; t < 4; t++) C[m][cc][t] = 0.f;

    u32 bAh = smaddr(sAh), bAl = smaddr(sAl);
    #pragma unroll
    for (int s = 0; s < 8; s++) {
        int k0 = s*16;
        u32 ah[4], al[4];
        ldsm4(ah[0],ah[1],ah[2],ah[3], a_addr(bAh, rw, k0, l, 272));
        ldsm4(al[0],al[1],al[2],al[3], a_addr(bAl, rw, k0, l, 272));
        #pragma unroll
        for (int m = 0; m < NMAT; m++) {
            #pragma unroll
            for (int cc = 0; cc < 4; cc++) {
                uint4 q = __ldg(&Fs[m][((nh*4+cc)*8 + s)*32 + l]);
                mma_bf16(C[m][cc], ah, q.x, q.y);
                mma_bf16(C[m][cc], ah, q.z, q.w);
                mma_bf16(C[m][cc], al, q.x, q.y);
            }
        }
    }

    float* Ys[3] = {Y0, Y1, (NMAT > 2) ? Y2 : Y0};
    #pragma unroll
    for (int m = 0; m < NMAT; m++) {
        #pragma unroll
        for (int cc = 0; cc < 4; cc++) {
            int col = nh*32 + cc*8 + 2*(l & 3);
            #pragma unroll
            for (int hr = 0; hr < 2; hr++) {
                int r = rw + (l >> 2) + hr*8;
                float v0 = C[m][cc][hr*2], v1 = C[m][cc][hr*2+1];
                if (EX) {
                    float xv = xc[r];
                    if (m == 0) { v0 += cb0[col]   + xv*rv0[col];
                                  v1 += cb0[col+1] + xv*rv0[col+1]; }
                    if (m == 1) { v0 += xv*rv1[col]; v1 += xv*rv1[col+1]; }
                    if (m == 2) { v0 += cb2[col];    v1 += cb2[col+1]; }
                }
                if (OUTBF) {
                    __nv_bfloat16 h0,l0,h1,l1;
                    split_bf(v0,h0,l0); split_bf(v1,h1,l1);
                    size_t o = (size_t)(row0+r)*DD + col;
                    *(u32*)(spl + (size_t)(2*m  )*NTOT*DD + o) = bfpack(h0,h1);
                    *(u32*)(spl + (size_t)(2*m+1)*NTOT*DD + o) = bfpack(l0,l1);
                } else {
                    *(float2*)(Ys[m] + (size_t)(row0+r)*DD + col) = make_float2(v0,v1);
                }
            }
        }
    }
}

// ---------------- Kernel 4: edge MLP via tensor cores (8 nodes/block) --------
// 512 threads, 128 edges. k2 fragment stream amortized over 2x edges.
__global__ void __launch_bounds__(512) k_edge_mma(
    const float* __restrict__ u_in, float* __restrict__ u_out,
    const float* __restrict__ base_, const float* __restrict__ proj,
    const float* __restrict__ loc, const int* __restrict__ idx,
    const uint4* __restrict__ F, const float* __restrict__ k2b,
    const float* __restrict__ k3w, const float* __restrict__ k3b)
{
    extern __shared__ __align__(16) unsigned char dynraw[];
    __nv_bfloat16* sHh = (__nv_bfloat16*)dynraw;          // 128*136
    __nv_bfloat16* sHl = sHh + 128*136;                   // 128*136
    float* bss = (float*)(sHl + 128*136);                 // 8*DD
    int*   js  = (int*)(bss + 8*DD);                      // 128
    float (*kvp)[2] = (float(*)[2])(js + 128);            // 128x2
    float* kvv = (float*)(kvp + 128);                     // 128

    int tid = threadIdx.x;
    int node0 = blockIdx.x*8;
    int bbase = node0 & ~(NN-1);
    if (tid < 256) ((float4*)bss)[tid] = ((const float4*)(base_ + (size_t)node0*DD))[tid];
    if (tid < 128) js[tid] = idx[node0*KK + tid];
    __syncthreads();

    #pragma unroll
    for (int it = 0; it < 8; it++) {
        int id2 = tid + it*512;
        int e = id2 >> 5, q = id2 & 31;
        int j = js[e];
        float4 p = *(const float4*)(proj + (size_t)(bbase+j)*DD + q*4);
        const float* bp = &bss[(e>>4)*DD + q*4];
        float h0 = fmaxf(p.x + bp[0], 0.f);
        float h1 = fmaxf(p.y + bp[1], 0.f);
        float h2 = fmaxf(p.z + bp[2], 0.f);
        float h3 = fmaxf(p.w + bp[3], 0.f);
        __nv_bfloat16 a0,a1,a2,a3,c0,c1,c2,c3;
        split_bf(h0,a0,c0); split_bf(h1,a1,c1); split_bf(h2,a2,c2); split_bf(h3,a3,c3);
        *(u32*)&sHh[e*136 + q*4]     = bfpack(a0,a1);
        *(u32*)&sHh[e*136 + q*4 + 2] = bfpack(a2,a3);
        *(u32*)&sHl[e*136 + q*4]     = bfpack(c0,c1);
        *(u32*)&sHl[e*136 + q*4 + 2] = bfpack(c2,c3);
    }
    __syncthreads();

    int l = tid & 31, w = tid >> 5;
    int mg = w >> 1, nh = w & 1;     // 8 edge-groups of 16, 2 col-halves
    int rw = mg*16, n0 = nh*64;
    float C[8][4];
    #pragma unroll
    for (int cc = 0; cc < 8; cc++)
        #pragma unroll
        for (int t = 0; t < 4; t++) C[cc][t] = 0.f;

    u32 bH = smaddr(sHh), bL = smaddr(sHl);
    #pragma unroll
    for (int s = 0; s < 8; s++) {
        int k0 = s*16;
        u32 ah[4], al[4];
        ldsm4(ah[0],ah[1],ah[2],ah[3], a_addr(bH, rw, k0, l, 272));
        ldsm4(al[0],al[1],al[2],al[3], a_addr(bL, rw, k0, l, 272));
        #pragma unroll
        for (int cc = 0; cc < 8; cc++) {
            uint4 q = __ldg(&F[((nh*8+cc)*8 + s)*32 + l]);
            mma_bf16(C[cc], ah, q.x, q.y);
            mma_bf16(C[cc], ah, q.z, q.w);
            mma_bf16(C[cc], al, q.x, q.y);
        }
    }

    float pr0 = 0.f, pr1 = 0.f;
    int ccl = 2*(l & 3);
    #pragma unroll
    for (int c = 0; c < 8; c++) {
        int col = n0 + c*8 + ccl;
        float b20 = __ldg(k2b+col), b21 = __ldg(k2b+col+1);
        float k30 = __ldg(k3w+col), k31 = __ldg(k3w+col+1);
        pr0 += fmaxf(C[c][0]+b20,0.f)*k30 + fmaxf(C[c][1]+b21,0.f)*k31;
        pr1 += fmaxf(C[c][2]+b20,0.f)*k30 + fmaxf(C[c][3]+b21,0.f)*k31;
    }
    pr0 += __shfl_xor_sync(0xffffffffu, pr0, 1);
    pr0 += __shfl_xor_sync(0xffffffffu, pr0, 2);
    pr1 += __shfl_xor_sync(0xffffffffu, pr1, 1);
    pr1 += __shfl_xor_sync(0xffffffffu, pr1, 2);
    if ((l & 3) == 0) {
        kvp[rw + (l>>2)    ][nh] = pr0;
        kvp[rw + (l>>2) + 8][nh] = pr1;
    }
    __syncthreads();
    if (tid < 128) kvv[tid] = (kvp[tid][0] + kvp[tid][1] + k3b[0])*0.25f;
    __syncthreads();

    // aggregation: 8 nodes x 128 dims on 512 threads (2 nodes each)
    int d = tid & 127;
    int gb = tid >> 7;
    #pragma unroll
    for (int gg = 0; gg < 2; gg++) {
        int g = gb + gg*4;
        int n = node0 + g;
        float a = 0.f;
        #pragma unroll
        for (int kk = 0; kk < KK; kk++)
            a = fmaf(kvv[g*KK+kk], u_in[(size_t)(bbase+js[g*KK+kk])*DD + d], a);
        float o = loc[(size_t)n*DD + d] + a + u_in[(size_t)n*DD + d];
        u_out[(size_t)n*DD + d] = fmaxf(o, 0.f);
    }
}

// ---------------- Kernel 5: decoder 64x64 tile via tensor cores --------------
__global__ void __launch_bounds__(256) k_dec_mma(
    const __nv_bfloat16* __restrict__ spl, float* __restrict__ out)
{
    extern __shared__ __align__(16) unsigned char dynraw[];
    __nv_bfloat16* sm = (__nv_bfloat16*)dynraw;   // 6 tiles of 64 x 136
    const int SB = 272;
    int tid = threadIdx.x;
    int bx = blockIdx.x, by = blockIdx.y, bz = blockIdx.z;
    size_t nb = (size_t)bz*NN;

    #pragma unroll
    for (int a2 = 0; a2 < 6; a2++) {
        size_t rowbase = nb + (size_t)((a2 < 4) ? by : bx)*64;
        const ull* src = (const ull*)(spl + (size_t)a2*NTOT*DD) + rowbase*32;
        ull* dst = (ull*)(sm + a2*64*136);
        #pragma unroll
        for (int it = 0; it < 8; it++) {
            int idx = tid + it*256;
            int r = idx >> 5, q = idx & 31;
            dst[r*34 + q] = src[r*32 + q];
        }
    }
    __syncthreads();

    int l = tid & 31, w = tid >> 5;
    int mg = w >> 1, nh = w & 1;
    int row0 = mg*16, n0 = nh*32;
    u32 base = smaddr(sm);
    u32 bVh = base, bVl = base + 17408, bWh = base + 2*17408,
        bWl = base + 3*17408, bUh = base + 4*17408, bUl = base + 5*17408;

    float cV[4][4] = {}, cW[4][4] = {};
    #pragma unroll
    for (int k0 = 0; k0 < 128; k0 += 16) {
        u32 vh[4], vl[4], wh[4], wl[4], uh[8], ul[8];
        ldsm4(vh[0],vh[1],vh[2],vh[3], a_addr(bVh, row0, k0, l, SB));
        ldsm4(vl[0],vl[1],vl[2],vl[3], a_addr(bVl, row0, k0, l, SB));
        ldsm4(wh[0],wh[1],wh[2],wh[3], a_addr(bWh, row0, k0, l, SB));
        ldsm4(wl[0],wl[1],wl[2],wl[3], a_addr(bWl, row0, k0, l, SB));
        {
            int g = l >> 3, r = l & 7;
            u32 a0 = bUh + (u32)((n0 + r + (g >> 1)*8)*SB + (k0 + (g & 1)*8)*2);
            u32 a1 = bUh + (u32)((n0 + 16 + r + (g >> 1)*8)*SB + (k0 + (g & 1)*8)*2);
            ldsm4(uh[0],uh[1],uh[2],uh[3], a0);
            ldsm4(uh[4],uh[5],uh[6],uh[7], a1);
            u32 a2 = bUl + (u32)((n0 + r + (g >> 1)*8)*SB + (k0 + (g & 1)*8)*2);
            u32 a3 = bUl + (u32)((n0 + 16 + r + (g >> 1)*8)*SB + (k0 + (g & 1)*8)*2);
            ldsm4(ul[0],ul[1],ul[2],ul[3], a2);
            ldsm4(ul[4],ul[5],ul[6],ul[7], a3);
        }
        #pragma unroll
        for (int c = 0; c < 4; c++) {
            mma_bf16(cV[c], vh, uh[2*c], uh[2*c+1]);
            mma_bf16(cV[c], vh, ul[2*c], ul[2*c+1]);
            mma_bf16(cV[c], vl, uh[2*c], uh[2*c+1]);
            mma_bf16(cW[c], wh, uh[2*c], uh[2*c+1]);
            mma_bf16(cW[c], wh, ul[2*c], ul[2*c+1]);
            mma_bf16(cW[c], wl, uh[2*c], uh[2*c+1]);
        }
    }

    size_t N2 = (size_t)NN*NN, S = (size_t)BB*N2;
    int r1 = by*64 + row0 + (l >> 2);
    int ccl = 2*(l & 3);
    #pragma unroll
    for (int c = 0; c < 4; c++) {
        int col = bx*64 + n0 + c*8 + ccl;
        #pragma unroll
        for (int hr = 0; hr < 2; hr++) {
            int row = r1 + hr*8;
            size_t o = (size_t)bz*N2 + (size_t)row*NN + col;
            float lg0 = cV[c][hr*2+0], lg1 = cV[c][hr*2+1];
            *(float2*)(out + o) = make_float2(lg0, lg1);
            float p0 = __fdividef(1.f, 1.f + __expf(-lg0));
            float p1 = __fdividef(1.f, 1.f + __expf(-lg1));
            *(float2*)(out + S + o) = make_float2(p0, p1);
            float w0 = cW[c][hr*2+0], w1 = cW[c][hr*2+1];
            float s0 = fmaxf(w0,0.f) + __logf(1.f + __expf(-fabsf(w0)));
            float s1 = fmaxf(w1,0.f) + __logf(1.f + __expf(-fabsf(w1)));
            *(float2*)(out + 2*S + o) = make_float2(s0, s1);
        }
    }
}

// ---------------- launch -----------------------------------------------------
extern "C" void kernel_launch(void* const* d_in, const int* in_sizes, int n_in,
                              void* d_out, int out_size)
{
    const float* spikes   = (const float*)d_in[0];
    const float* coords   = (const float*)d_in[1];
    const float* conv_w   = (const float*)d_in[2];
    const float* conv_b   = (const float*)d_in[3];
    const float* fc_w     = (const float*)d_in[4];
    const float* fc_b     = (const float*)d_in[5];
    const float* local_w  = (const float*)d_in[6];
    const float* local_b  = (const float*)d_in[7];
    const float* k1_w     = (const float*)d_in[8];
    const float* k1_b     = (const float*)d_in[9];
    const float* k2_w     = (const float*)d_in[10];
    const float* k2_b     = (const float*)d_in[11];
    const float* k3_w     = (const float*)d_in[12];
    const float* k3_b     = (const float*)d_in[13];
    const float* W_logits = (const float*)d_in[14];
    const float* W_weight = (const float*)d_in[15];
    float* out = (float*)d_out;

    float *u0, *u1, *pb, *pp, *pl; int *pix, *ppos; ull *wpk, *pskey;
    __nv_bfloat16 *spl; uint4 *wfrag;
    cudaGetSymbolAddress((void**)&u0,    g_u);
    cudaGetSymbolAddress((void**)&u1,    g_u2);
    cudaGetSymbolAddress((void**)&pb,    g_base);
    cudaGetSymbolAddress((void**)&pp,    g_proj);
    cudaGetSymbolAddress((void**)&pl,    g_loc);
    cudaGetSymbolAddress((void**)&pix,   g_idx);
    cudaGetSymbolAddress((void**)&ppos,  g_pos);
    cudaGetSymbolAddress((void**)&pskey, g_skey);
    cudaGetSymbolAddress((void**)&wpk,   g_wpack);
    cudaGetSymbolAddress((void**)&spl,   g_spl);
    cudaGetSymbolAddress((void**)&wfrag, g_wfrag);

    cudaFuncSetAttribute(k_dec_mma,  cudaFuncAttributeMaxDynamicSharedMemorySize, 104448);
    cudaFuncSetAttribute(k_edge_mma, cudaFuncAttributeMaxDynamicSharedMemorySize, 75776);

    WF wf;
    for (int lyr = 0; lyr < 3; lyr++) {
        wf.p[4*lyr+0] = k1_w + (size_t)lyr*258*DD + 2*DD;
        wf.p[4*lyr+1] = k1_w + (size_t)lyr*258*DD + 130*DD;
        wf.p[4*lyr+2] = local_w + (size_t)lyr*DD*DD;
        wf.p[4*lyr+3] = k2_w + (size_t)lyr*DD*DD;
    }
    wf.p[12] = W_logits;
    wf.p[13] = W_weight;
    wf.p[14] = fc_w;

    // launch order: pack(1), lift(2), rank(3), node0(4 <- profiled slot),
    // knn2(5), edge0(6), ...
    k_pack<<<dim3(64,15), 128>>>(wf, wfrag, (float2*)wpk);
    k_lift<<<NTOT/2, 128>>>(spikes, conv_w, conv_b, wpk, fc_b, u0);
    k_rank<<<dim3(NN/8, BB), 256>>>(coords, pskey, ppos);

    float* ucur = u0;
    float* unext = u1;
    for (int lyr = 0; lyr < 3; lyr++) {
        const float* W1 = k1_w + (size_t)lyr*258*DD;
        k_node_mma<3, true, false><<<NTOT/32, 256>>>(ucur,
            wfrag + (size_t)(4*lyr+0)*4096, wfrag + (size_t)(4*lyr+1)*4096,
            wfrag + (size_t)(4*lyr+2)*4096,
            k1_b + lyr*DD, local_b + lyr*DD,
            W1, W1 + DD, coords,
            pb, pp, pl, nullptr);
        if (lyr == 0)
            k_knn2<<<dim3(NN/128, BB), 128>>>(pskey, ppos, pix);
        k_edge_mma<<<NTOT/8, 512, 75776>>>(ucur, unext, pb, pp, pl, pix,
            wfrag + (size_t)(4*lyr+3)*4096,
            k2_b + lyr*DD, k3_w + (size_t)lyr*DD, k3_b + lyr);
        float* t = ucur; ucur = unext; unext = t;
    }

    k_node_mma<2, false, true><<<NTOT/32, 256>>>(ucur,
        wfrag + (size_t)12*4096, wfrag + (size_t)13*4096, wfrag,
        nullptr, nullptr, nullptr, nullptr, nullptr,
        nullptr, nullptr, nullptr, spl);
    k_dec_mma<<<dim3(NN/64, NN/64, BB), 256, 104448>>>(spl, out);
}

// round 15
// speedup vs baseline: 1.2172x; 1.2172x over previous
#include <cuda_runtime.h>
#include <cuda_bf16.h>
#include <math.h>

#define BB 2
#define NN 2048
#define TT 256
#define DD 128
#define KK 16
#define NTOT (BB*NN)

typedef unsigned long long ull;
typedef unsigned int u32;

// ---------------- scalar f32x2 helpers ----------------
__device__ __forceinline__ ull ffma2(ull a, ull b, ull c){
    ull d; asm("fma.rn.f32x2 %0, %1, %2, %3;" : "=l"(d) : "l"(a), "l"(b), "l"(c));
    return d;
}
__device__ __forceinline__ float usum(ull v){
    float lo, hi; asm("mov.b64 {%0,%1}, %2;" : "=f"(lo), "=f"(hi) : "l"(v));
    return lo + hi;
}
__device__ __forceinline__ float ulo(ull v){
    float lo, hi; asm("mov.b64 {%0,%1}, %2;" : "=f"(lo), "=f"(hi) : "l"(v));
    return lo;
}
__device__ __forceinline__ float uhi(ull v){
    float lo, hi; asm("mov.b64 {%0,%1}, %2;" : "=f"(lo), "=f"(hi) : "l"(v));
    return hi;
}
__device__ __forceinline__ ull pk(float lo, float hi){
    ull r; asm("mov.b64 %0, {%1,%2};" : "=l"(r) : "f"(lo), "f"(hi));
    return r;
}

// ---------------- mma helpers ----------------
__device__ __forceinline__ u32 smaddr(const void* p){
    return (u32)__cvta_generic_to_shared(p);
}
__device__ __forceinline__ void ldsm4(u32 &r0,u32 &r1,u32 &r2,u32 &r3, u32 a){
    asm volatile("ldmatrix.sync.aligned.m8n8.x4.shared.b16 {%0,%1,%2,%3}, [%4];"
                 : "=r"(r0),"=r"(r1),"=r"(r2),"=r"(r3) : "r"(a));
}
__device__ __forceinline__ void mma_bf16(float* c, const u32* a, u32 b0, u32 b1){
    asm volatile("mma.sync.aligned.m16n8k16.row.col.f32.bf16.bf16.f32 "
        "{%0,%1,%2,%3},{%4,%5,%6,%7},{%8,%9},{%0,%1,%2,%3};"
        : "+f"(c[0]),"+f"(c[1]),"+f"(c[2]),"+f"(c[3])
        : "r"(a[0]),"r"(a[1]),"r"(a[2]),"r"(a[3]),"r"(b0),"r"(b1));
}
__device__ __forceinline__ u32 a_addr(u32 base, int row0, int k0, int lane, int sB){
    int g = lane >> 3, r = lane & 7;
    return base + (u32)((row0 + r + (g & 1)*8)*sB + (k0 + (g >> 1)*8)*2);
}
__device__ __forceinline__ void split_bf(float x, __nv_bfloat16 &h, __nv_bfloat16 &l){
    h = __float2bfloat16(x);
    l = __float2bfloat16(x - __bfloat162float(h));
}
__device__ __forceinline__ u32 bfpack(__nv_bfloat16 a, __nv_bfloat16 b){
    __nv_bfloat162 t; t.x = a; t.y = b; return *(u32*)&t;
}

// ---------------- scratch ----------------
__device__ float g_u   [NTOT*DD];
__device__ float g_u2  [NTOT*DD];
__device__ float g_base[NTOT*DD];
__device__ float g_proj[NTOT*DD];
__device__ float g_loc [NTOT*DD];
__device__ int   g_idx [NTOT*KK];
__device__ ull   g_skey[NTOT];
__device__ int   g_pos [NTOT];
__device__ __align__(16) ull g_wpack[64*128];                // fc_w k-pair pack
__device__ __align__(16) uint4 g_wfrag[14*4096];             // mma B-fragment packs
__device__ __align__(16) __nv_bfloat16 g_spl[6*NTOT*DD];     // vh,vl,wh,wl,uh,ul

// ---------------- Kernel 0: merged weight packs -------------------------------
struct WF { const float* p[15]; };
__global__ void __launch_bounds__(128) k_pack(WF wf, uint4* __restrict__ dst,
                                              float2* __restrict__ fcdst){
    int m = blockIdx.y;
    if (m == 14) {
        const float* W = wf.p[14];
        int i = blockIdx.x*128 + threadIdx.x;
        int kp = i >> 7, c = i & 127;
        fcdst[i] = make_float2(W[(2*kp)*DD + c], W[(2*kp+1)*DD + c]);
        return;
    }
    if (blockIdx.x >= 32) return;
    const float* W = wf.p[m];
    int l = threadIdx.x & 31;
    int pair = blockIdx.x*4 + (threadIdx.x >> 5);
    int c = pair >> 3, s = pair & 7;
    int kk = s*16 + 2*(l & 3);
    int nn = c*8 + (l >> 2);
    float w00 = W[(size_t)kk*DD + nn],     w01 = W[(size_t)(kk+1)*DD + nn];
    float w10 = W[(size_t)(kk+8)*DD + nn], w11 = W[(size_t)(kk+9)*DD + nn];
    __nv_bfloat16 h00,h01,h10,h11,l00,l01,l10,l11;
    split_bf(w00,h00,l00); split_bf(w01,h01,l01);
    split_bf(w10,h10,l10); split_bf(w11,h11,l11);
    uint4 q;
    q.x = bfpack(h00,h01); q.y = bfpack(h10,h11);
    q.z = bfpack(l00,l01); q.w = bfpack(l10,l11);
    dst[(size_t)m*4096 + pair*32 + l] = q;
}

// ---------------- Kernel 1: TemporalLift — channel-pair f32x2 ----------------
__global__ void __launch_bounds__(128) k_lift(
    const float* __restrict__ spikes, const float* __restrict__ conv_w,
    const float* __restrict__ conv_b, const ull* __restrict__ fcp,
    const float* __restrict__ fc_b, float* __restrict__ u)
{
    __shared__ __align__(16) ull sp2[2][TT+8];
    __shared__ __align__(16) float xm[2][DD];
    __shared__ float warpsum[4];
    int node0 = blockIdx.x*2;
    int tid = threadIdx.x;
    int nd = tid >> 6;
    int q  = tid & 63;

    const float* s = spikes + (size_t)(node0+nd)*TT;
    float v0 = s[q], v1 = s[q+64], v2 = s[q+128], v3 = s[q+192];
    sp2[nd][2+q]      = pk(v0,v0);
    sp2[nd][2+q+64]   = pk(v1,v1);
    sp2[nd][2+q+128]  = pk(v2,v2);
    sp2[nd][2+q+192]  = pk(v3,v3);
    if (q < 2) sp2[nd][q] = 0ull;
    if (q < 6) sp2[nd][TT+2+q] = 0ull;

    float part = v0 + v1 + v2 + v3;
    #pragma unroll
    for (int sft = 16; sft > 0; sft >>= 1)
        part += __shfl_xor_sync(0xffffffffu, part, sft);
    if ((tid & 31) == 0) warpsum[tid >> 5] = part;
    __syncthreads();
    float S = warpsum[2*nd] + warpsum[2*nd+1];

    int c0 = q, c1 = q + 64;
    float w0a = conv_w[c0*5+0], w1a = conv_w[c0*5+1], w2a = conv_w[c0*5+2],
          w3a = conv_w[c0*5+3], w4a = conv_w[c0*5+4];
    float w0b = conv_w[c1*5+0], w1b = conv_w[c1*5+1], w2b = conv_w[c1*5+2],
          w3b = conv_w[c1*5+3], w4b = conv_w[c1*5+4];
    float bba = conv_b[c0], bbb = conv_b[c1];
    ull w0p = pk(w0a,w0b), w1p = pk(w1a,w1b), w2p = pk(w2a,w2b),
        w3p = pk(w3a,w3b), w4p = pk(w4a,w4b), bbp = pk(bba,bbb);
    const ull ONE2 = 0x3f8000003f800000ULL;
    const ull MASK = 0x7fffffff7fffffffULL;

    ull acc2 = 0ull;
    ulonglong2 A = *(const ulonglong2*)&sp2[nd][0];
    ulonglong2 B = *(const ulonglong2*)&sp2[nd][2];
    #pragma unroll 8
    for (int x = 0; x < 256; x += 4) {
        ulonglong2 Cq = *(const ulonglong2*)&sp2[nd][x+4];
        ulonglong2 Dq = *(const ulonglong2*)&sp2[nd][x+6];
        ull d0 = A.x, d1 = A.y, d2 = B.x, d3 = B.y;
        ull d4 = Cq.x, d5 = Cq.y, d6 = Dq.x, d7 = Dq.y;
        ull o0 = ffma2(w4p,d4, ffma2(w3p,d3, ffma2(w2p,d2, ffma2(w1p,d1, ffma2(w0p,d0, bbp)))));
        ull o1 = ffma2(w4p,d5, ffma2(w3p,d4, ffma2(w2p,d3, ffma2(w1p,d2, ffma2(w0p,d1, bbp)))));
        ull o2 = ffma2(w4p,d6, ffma2(w3p,d5, ffma2(w2p,d4, ffma2(w1p,d3, ffma2(w0p,d2, bbp)))));
        ull o3 = ffma2(w4p,d7, ffma2(w3p,d6, ffma2(w2p,d5, ffma2(w1p,d4, ffma2(w0p,d3, bbp)))));
        acc2 = ffma2(o0 & MASK, ONE2, acc2);
        acc2 = ffma2(o1 & MASK, ONE2, acc2);
        acc2 = ffma2(o2 & MASK, ONE2, acc2);
        acc2 = ffma2(o3 & MASK, ONE2, acc2);
        A = Cq; B = Dq;
    }
    float sa = ulo(acc2), sb = uhi(acc2);
    float s0 = ulo(sp2[nd][2]),   s1 = ulo(sp2[nd][3]);
    float s254 = ulo(sp2[nd][256]), s255 = ulo(sp2[nd][257]);
    float lina = 256.f*bba
               + w0a*(S - s254 - s255) + w1a*(S - s255) + w2a*S
               + w3a*(S - s0) + w4a*(S - s0 - s1);
    float linb = 256.f*bbb
               + w0b*(S - s254 - s255) + w1b*(S - s255) + w2b*S
               + w3b*(S - s0) + w4b*(S - s0 - s1);
    xm[nd][c0] = (lina + sa) * (0.5f/256.f);
    xm[nd][c1] = (linb + sb) * (0.5f/256.f);
    __syncthreads();

    int h = tid;
    ull oa = 0ull, ob = 0ull;
    #pragma unroll 8
    for (int kp = 0; kp < 64; kp++) {
        ull wv = __ldg(&fcp[kp*DD + h]);
        oa = ffma2(*(const ull*)&xm[0][2*kp], wv, oa);
        ob = ffma2(*(const ull*)&xm[1][2*kp], wv, ob);
    }
    float fb = fc_b[h];
    u[(size_t)node0*DD + h]     = fmaxf(usum(oa) + fb, 0.f);
    u[(size_t)(node0+1)*DD + h] = fmaxf(usum(ob) + fb, 0.f);
}

// ---------------- Kernel 2a: rank-by-counting ---------------------------------
__global__ void __launch_bounds__(256) k_rank(
    const float* __restrict__ coords, ull* __restrict__ skey, int* __restrict__ pos)
{
    __shared__ float c[NN];
    int b = blockIdx.y;
    const float* cb = coords + (size_t)b*NN;
    for (int j = threadIdx.x; j < NN; j += 256) c[j] = cb[j];
    __syncthreads();
    int w = threadIdx.x >> 5, l = threadIdx.x & 31;
    int i = blockIdx.x*8 + w;
    float ci = c[i];
    u32 cib = __float_as_uint(ci);
    int cnt = 0;
    #pragma unroll 4
    for (int t = 0; t < NN/32; t++) {
        int j = t*32 + l;
        u32 cjb = __float_as_uint(c[j]);
        cnt += (cjb < cib) || (cjb == cib && j < i);
    }
    #pragma unroll
    for (int s = 16; s > 0; s >>= 1)
        cnt += __shfl_xor_sync(0xffffffffu, cnt, s);
    if (l == 0) {
        skey[(size_t)b*NN + cnt] = ((ull)cib << 32) | (u32)i;
        pos[(size_t)b*NN + i] = cnt;
    }
}

// ---------------- Kernel 2b: kNN via two-pointer window (128-thr blocks) -----
__global__ void __launch_bounds__(128) k_knn2(
    const ull* __restrict__ skey, const int* __restrict__ pos, int* __restrict__ idx)
{
    __shared__ ull sk[NN];
    int b = blockIdx.y;
    for (int i = threadIdx.x; i < NN; i += 128) sk[i] = skey[(size_t)b*NN + i];
    __syncthreads();
    int i = blockIdx.x*128 + threadIdx.x;
    int p = pos[(size_t)b*NN + i];
    float ci = __uint_as_float((u32)(sk[p] >> 32));
    int lo = p, hi = p + 1;
    int* o = idx + ((size_t)b*NN + i)*KK;
    #pragma unroll
    for (int r = 0; r < KK; r++) {
        ull cl = ~0ull, ch = ~0ull;
        if (lo >= 0) {
            ull v = sk[lo];
            float d = __uint_as_float((u32)(v >> 32)) - ci;
            cl = ((ull)__float_as_uint(d*d) << 32) | (v & 0xffffffffull);
        }
        if (hi < NN) {
            ull v = sk[hi];
            float d = __uint_as_float((u32)(v >> 32)) - ci;
            ch = ((ull)__float_as_uint(d*d) << 32) | (v & 0xffffffffull);
        }
        if (cl <= ch) { o[r] = (int)(cl & 0xffffffffull); lo--; }
        else          { o[r] = (int)(ch & 0xffffffffull); hi++; }
    }
}

// ---------------- Kernel 3: node GEMMs, 16-row blocks, warp = 16 cols --------
// grid = NTOT/16 = 256 blocks (all SMs busy, 2 blocks/SM). Warp nh handles
// cols [nh*16, nh*16+16): C = NMAT x 2 x 4 regs, 48 fragment LDG.128s.
template<int NMAT, bool EX, bool OUTBF>
__global__ void __launch_bounds__(256) k_node_mma(
    const float* __restrict__ X,
    const uint4* __restrict__ F0, const uint4* __restrict__ F1,
    const uint4* __restrict__ F2,
    const float* __restrict__ cb0, const float* __restrict__ cb2,
    const float* __restrict__ rv0, const float* __restrict__ rv1,
    const float* __restrict__ xs,
    float* __restrict__ Y0, float* __restrict__ Y1, float* __restrict__ Y2,
    __nv_bfloat16* __restrict__ spl)
{
    __shared__ __align__(16) __nv_bfloat16 sAh[16*136];
    __shared__ __align__(16) __nv_bfloat16 sAl[16*136];
    __shared__ float xc[16];
    int tid = threadIdx.x;
    int row0 = blockIdx.x*16;

    #pragma unroll
    for (int it = 0; it < 2; it++) {
        int idx = tid + it*256;
        int r = idx >> 5, q = idx & 31;
        float4 v = *(const float4*)(X + (size_t)(row0+r)*DD + q*4);
        __nv_bfloat16 h0,h1,h2,h3,l0,l1,l2,l3;
        split_bf(v.x,h0,l0); split_bf(v.y,h1,l1);
        split_bf(v.z,h2,l2); split_bf(v.w,h3,l3);
        u32 ph0 = bfpack(h0,h1), ph1 = bfpack(h2,h3);
        u32 pl0 = bfpack(l0,l1), pl1 = bfpack(l2,l3);
        *(u32*)&sAh[r*136 + q*4]     = ph0;
        *(u32*)&sAh[r*136 + q*4 + 2] = ph1;
        *(u32*)&sAl[r*136 + q*4]     = pl0;
        *(u32*)&sAl[r*136 + q*4 + 2] = pl1;
        if (OUTBF) {
            size_t o = (size_t)(row0+r)*DD + q*4;
            *(u32*)(spl + (size_t)4*NTOT*DD + o)     = ph0;
            *(u32*)(spl + (size_t)4*NTOT*DD + o + 2) = ph1;
            *(u32*)(spl + (size_t)5*NTOT*DD + o)     = pl0;
            *(u32*)(spl + (size_t)5*NTOT*DD + o + 2) = pl1;
        }
    }
    if (EX && tid < 16) xc[tid] = xs[row0 + tid];
    __syncthreads();

    int l = tid & 31, nh = tid >> 5;   // 8 warps = 8 col-sixteenths
    const uint4* Fs[3] = {F0, F1, (NMAT > 2) ? F2 : F0};
    float C[NMAT][2][4];
    #pragma unroll
    for (int m = 0; m < NMAT; m++)
        #pragma unroll
        for (int cc = 0; cc < 2; cc++)
            #pragma unroll
            for (int t = 0; t < 4; t++) C[m][cc][t] = 0.f;

    u32 bAh = smaddr(sAh), bAl = smaddr(sAl);
    #pragma unroll
    for (int s = 0; s < 8; s++) {
        int k0 = s*16;
        u32 ah[4], al[4];
        ldsm4(ah[0],ah[1],ah[2],ah[3], a_addr(bAh, 0, k0, l, 272));
        ldsm4(al[0],al[1],al[2],al[3], a_addr(bAl, 0, k0, l, 272));
        #pragma unroll
        for (int m = 0; m < NMAT; m++) {
            #pragma unroll
            for (int cc = 0; cc < 2; cc++) {
                uint4 q = __ldg(&Fs[m][((nh*2+cc)*8 + s)*32 + l]);
                mma_bf16(C[m][cc], ah, q.x, q.y);
                mma_bf16(C[m][cc], ah, q.z, q.w);
                mma_bf16(C[m][cc], al, q.x, q.y);
            }
        }
    }

    float* Ys[3] = {Y0, Y1, (NMAT > 2) ? Y2 : Y0};
    #pragma unroll
    for (int m = 0; m < NMAT; m++) {
        #pragma unroll
        for (int cc = 0; cc < 2; cc++) {
            int col = nh*16 + cc*8 + 2*(l & 3);
            #pragma unroll
            for (int hr = 0; hr < 2; hr++) {
                int r = (l >> 2) + hr*8;
                float v0 = C[m][cc][hr*2], v1 = C[m][cc][hr*2+1];
                if (EX) {
                    float xv = xc[r];
                    if (m == 0) { v0 += cb0[col]   + xv*rv0[col];
                                  v1 += cb0[col+1] + xv*rv0[col+1]; }
                    if (m == 1) { v0 += xv*rv1[col]; v1 += xv*rv1[col+1]; }
                    if (m == 2) { v0 += cb2[col];    v1 += cb2[col+1]; }
                }
                if (OUTBF) {
                    __nv_bfloat16 h0,l0,h1,l1;
                    split_bf(v0,h0,l0); split_bf(v1,h1,l1);
                    size_t o = (size_t)(row0+r)*DD + col;
                    *(u32*)(spl + (size_t)(2*m  )*NTOT*DD + o) = bfpack(h0,h1);
                    *(u32*)(spl + (size_t)(2*m+1)*NTOT*DD + o) = bfpack(l0,l1);
                } else {
                    *(float2*)(Ys[m] + (size_t)(row0+r)*DD + col) = make_float2(v0,v1);
                }
            }
        }
    }
}

// ---------------- Kernel 4: edge MLP via tensor cores (R13: 4 nodes/block) ---
__global__ void __launch_bounds__(256) k_edge_mma(
    const float* __restrict__ u_in, float* __restrict__ u_out,
    const float* __restrict__ base_, const float* __restrict__ proj,
    const float* __restrict__ loc, const int* __restrict__ idx,
    const uint4* __restrict__ F, const float* __restrict__ k2b,
    const float* __restrict__ k3w, const float* __restrict__ k3b)
{
    __shared__ __align__(16) __nv_bfloat16 sHh[64*136];
    __shared__ __align__(16) __nv_bfloat16 sHl[64*136];
    __shared__ __align__(16) float bss[4*DD];
    __shared__ int   js[64];
    __shared__ float kvp[64][2];
    __shared__ float kvv[64];

    int tid = threadIdx.x;
    int node0 = blockIdx.x*4;
    int bbase = node0 & ~(NN-1);
    if (tid < 128) ((float4*)bss)[tid] = ((const float4*)(base_ + (size_t)node0*DD))[tid];
    if (tid < 64) js[tid] = idx[node0*KK + tid];
    __syncthreads();

    #pragma unroll
    for (int it = 0; it < 8; it++) {
        int id2 = tid + it*256;
        int e = id2 >> 5, q = id2 & 31;
        int j = js[e];
        float4 p = *(const float4*)(proj + (size_t)(bbase+j)*DD + q*4);
        const float* bp = &bss[(e>>4)*DD + q*4];
        float h0 = fmaxf(p.x + bp[0], 0.f);
        float h1 = fmaxf(p.y + bp[1], 0.f);
        float h2 = fmaxf(p.z + bp[2], 0.f);
        float h3 = fmaxf(p.w + bp[3], 0.f);
        __nv_bfloat16 a0,a1,a2,a3,c0,c1,c2,c3;
        split_bf(h0,a0,c0); split_bf(h1,a1,c1); split_bf(h2,a2,c2); split_bf(h3,a3,c3);
        *(u32*)&sHh[e*136 + q*4]     = bfpack(a0,a1);
        *(u32*)&sHh[e*136 + q*4 + 2] = bfpack(a2,a3);
        *(u32*)&sHl[e*136 + q*4]     = bfpack(c0,c1);
        *(u32*)&sHl[e*136 + q*4 + 2] = bfpack(c2,c3);
    }
    __syncthreads();

    int l = tid & 31, w = tid >> 5;
    int mg = w >> 1, nh = w & 1;
    int rw = mg*16, n0 = nh*64;
    float C[8][4];
    #pragma unroll
    for (int cc = 0; cc < 8; cc++)
        #pragma unroll
        for (int t = 0; t < 4; t++) C[cc][t] = 0.f;

    u32 bH = smaddr(sHh), bL = smaddr(sHl);
    #pragma unroll
    for (int s = 0; s < 8; s++) {
        int k0 = s*16;
        u32 ah[4], al[4];
        ldsm4(ah[0],ah[1],ah[2],ah[3], a_addr(bH, rw, k0, l, 272));
        ldsm4(al[0],al[1],al[2],al[3], a_addr(bL, rw, k0, l, 272));
        #pragma unroll
        for (int cc = 0; cc < 8; cc++) {
            uint4 q = __ldg(&F[((nh*8+cc)*8 + s)*32 + l]);
            mma_bf16(C[cc], ah, q.x, q.y);
            mma_bf16(C[cc], ah, q.z, q.w);
            mma_bf16(C[cc], al, q.x, q.y);
        }
    }

    float pr0 = 0.f, pr1 = 0.f;
    int ccl = 2*(l & 3);
    #pragma unroll
    for (int c = 0; c < 8; c++) {
        int col = n0 + c*8 + ccl;
        float b20 = __ldg(k2b+col), b21 = __ldg(k2b+col+1);
        float k30 = __ldg(k3w+col), k31 = __ldg(k3w+col+1);
        pr0 += fmaxf(C[c][0]+b20,0.f)*k30 + fmaxf(C[c][1]+b21,0.f)*k31;
        pr1 += fmaxf(C[c][2]+b20,0.f)*k30 + fmaxf(C[c][3]+b21,0.f)*k31;
    }
    pr0 += __shfl_xor_sync(0xffffffffu, pr0, 1);
    pr0 += __shfl_xor_sync(0xffffffffu, pr0, 2);
    pr1 += __shfl_xor_sync(0xffffffffu, pr1, 1);
    pr1 += __shfl_xor_sync(0xffffffffu, pr1, 2);
    if ((l & 3) == 0) {
        kvp[rw + (l>>2)    ][nh] = pr0;
        kvp[rw + (l>>2) + 8][nh] = pr1;
    }
    __syncthreads();
    if (tid < 64) kvv[tid] = (kvp[tid][0] + kvp[tid][1] + k3b[0])*0.25f;
    __syncthreads();

    int d = tid & 127;
    #pragma unroll
    for (int gg = 0; gg < 4; gg += 2) {
        int g = gg + (tid >> 7);
        int n = node0 + g;
        float a = 0.f;
        #pragma unroll
        for (int kk = 0; kk < KK; kk++)
            a = fmaf(kvv[g*KK+kk], u_in[(size_t)(bbase+js[g*KK+kk])*DD + d], a);
        float o = loc[(size_t)n*DD + d] + a + u_in[(size_t)n*DD + d];
        u_out[(size_t)n*DD + d] = fmaxf(o, 0.f);
    }
}

// ---------------- Kernel 5: decoder 64x64 tile via tensor cores --------------
__global__ void __launch_bounds__(256) k_dec_mma(
    const __nv_bfloat16* __restrict__ spl, float* __restrict__ out)
{
    extern __shared__ __align__(16) unsigned char dynraw[];
    __nv_bfloat16* sm = (__nv_bfloat16*)dynraw;   // 6 tiles of 64 x 136
    const int SB = 272;
    int tid = threadIdx.x;
    int bx = blockIdx.x, by = blockIdx.y, bz = blockIdx.z;
    size_t nb = (size_t)bz*NN;

    #pragma unroll
    for (int a2 = 0; a2 < 6; a2++) {
        size_t rowbase = nb + (size_t)((a2 < 4) ? by : bx)*64;
        const ull* src = (const ull*)(spl + (size_t)a2*NTOT*DD) + rowbase*32;
        ull* dst = (ull*)(sm + a2*64*136);
        #pragma unroll
        for (int it = 0; it < 8; it++) {
            int idx = tid + it*256;
            int r = idx >> 5, q = idx & 31;
            dst[r*34 + q] = src[r*32 + q];
        }
    }
    __syncthreads();

    int l = tid & 31, w = tid >> 5;
    int mg = w >> 1, nh = w & 1;
    int row0 = mg*16, n0 = nh*32;
    u32 base = smaddr(sm);
    u32 bVh = base, bVl = base + 17408, bWh = base + 2*17408,
        bWl = base + 3*17408, bUh = base + 4*17408, bUl = base + 5*17408;

    float cV[4][4] = {}, cW[4][4] = {};
    #pragma unroll
    for (int k0 = 0; k0 < 128; k0 += 16) {
        u32 vh[4], vl[4], wh[4], wl[4], uh[8], ul[8];
        ldsm4(vh[0],vh[1],vh[2],vh[3], a_addr(bVh, row0, k0, l, SB));
        ldsm4(vl[0],vl[1],vl[2],vl[3], a_addr(bVl, row0, k0, l, SB));
        ldsm4(wh[0],wh[1],wh[2],wh[3], a_addr(bWh, row0, k0, l, SB));
        ldsm4(wl[0],wl[1],wl[2],wl[3], a_addr(bWl, row0, k0, l, SB));
        {
            int g = l >> 3, r = l & 7;
            u32 a0 = bUh + (u32)((n0 + r + (g >> 1)*8)*SB + (k0 + (g & 1)*8)*2);
            u32 a1 = bUh + (u32)((n0 + 16 + r + (g >> 1)*8)*SB + (k0 + (g & 1)*8)*2);
            ldsm4(uh[0],uh[1],uh[2],uh[3], a0);
            ldsm4(uh[4],uh[5],uh[6],uh[7], a1);
            u32 a2 = bUl + (u32)((n0 + r + (g >> 1)*8)*SB + (k0 + (g & 1)*8)*2);
            u32 a3 = bUl + (u32)((n0 + 16 + r + (g >> 1)*8)*SB + (k0 + (g & 1)*8)*2);
            ldsm4(ul[0],ul[1],ul[2],ul[3], a2);
            ldsm4(ul[4],ul[5],ul[6],ul[7], a3);
        }
        #pragma unroll
        for (int c = 0; c < 4; c++) {
            mma_bf16(cV[c], vh, uh[2*c], uh[2*c+1]);
            mma_bf16(cV[c], vh, ul[2*c], ul[2*c+1]);
            mma_bf16(cV[c], vl, uh[2*c], uh[2*c+1]);
            mma_bf16(cW[c], wh, uh[2*c], uh[2*c+1]);
            mma_bf16(cW[c], wh, ul[2*c], ul[2*c+1]);
            mma_bf16(cW[c], wl, uh[2*c], uh[2*c+1]);
        }
    }

    size_t N2 = (size_t)NN*NN, S = (size_t)BB*N2;
    int r1 = by*64 + row0 + (l >> 2);
    int ccl = 2*(l & 3);
    #pragma unroll
    for (int c = 0; c < 4; c++) {
        int col = bx*64 + n0 + c*8 + ccl;
        #pragma unroll
        for (int hr = 0; hr < 2; hr++) {
            int row = r1 + hr*8;
            size_t o = (size_t)bz*N2 + (size_t)row*NN + col;
            float lg0 = cV[c][hr*2+0], lg1 = cV[c][hr*2+1];
            *(float2*)(out + o) = make_float2(lg0, lg1);
            float p0 = __fdividef(1.f, 1.f + __expf(-lg0));
            float p1 = __fdividef(1.f, 1.f + __expf(-lg1));
            *(float2*)(out + S + o) = make_float2(p0, p1);
            float w0 = cW[c][hr*2+0], w1 = cW[c][hr*2+1];
            float s0 = fmaxf(w0,0.f) + __logf(1.f + __expf(-fabsf(w0)));
            float s1 = fmaxf(w1,0.f) + __logf(1.f + __expf(-fabsf(w1)));
            *(float2*)(out + 2*S + o) = make_float2(s0, s1);
        }
    }
}

// ---------------- launch -----------------------------------------------------
extern "C" void kernel_launch(void* const* d_in, const int* in_sizes, int n_in,
                              void* d_out, int out_size)
{
    const float* spikes   = (const float*)d_in[0];
    const float* coords   = (const float*)d_in[1];
    const float* conv_w   = (const float*)d_in[2];
    const float* conv_b   = (const float*)d_in[3];
    const float* fc_w     = (const float*)d_in[4];
    const float* fc_b     = (const float*)d_in[5];
    const float* local_w  = (const float*)d_in[6];
    const float* local_b  = (const float*)d_in[7];
    const float* k1_w     = (const float*)d_in[8];
    const float* k1_b     = (const float*)d_in[9];
    const float* k2_w     = (const float*)d_in[10];
    const float* k2_b     = (const float*)d_in[11];
    const float* k3_w     = (const float*)d_in[12];
    const float* k3_b     = (const float*)d_in[13];
    const float* W_logits = (const float*)d_in[14];
    const float* W_weight = (const float*)d_in[15];
    float* out = (float*)d_out;

    float *u0, *u1, *pb, *pp, *pl; int *pix, *ppos; ull *wpk, *pskey;
    __nv_bfloat16 *spl; uint4 *wfrag;
    cudaGetSymbolAddress((void**)&u0,    g_u);
    cudaGetSymbolAddress((void**)&u1,    g_u2);
    cudaGetSymbolAddress((void**)&pb,    g_base);
    cudaGetSymbolAddress((void**)&pp,    g_proj);
    cudaGetSymbolAddress((void**)&pl,    g_loc);
    cudaGetSymbolAddress((void**)&pix,   g_idx);
    cudaGetSymbolAddress((void**)&ppos,  g_pos);
    cudaGetSymbolAddress((void**)&pskey, g_skey);
    cudaGetSymbolAddress((void**)&wpk,   g_wpack);
    cudaGetSymbolAddress((void**)&spl,   g_spl);
    cudaGetSymbolAddress((void**)&wfrag, g_wfrag);

    cudaFuncSetAttribute(k_dec_mma, cudaFuncAttributeMaxDynamicSharedMemorySize, 104448);

    WF wf;
    for (int lyr = 0; lyr < 3; lyr++) {
        wf.p[4*lyr+0] = k1_w + (size_t)lyr*258*DD + 2*DD;
        wf.p[4*lyr+1] = k1_w + (size_t)lyr*258*DD + 130*DD;
        wf.p[4*lyr+2] = local_w + (size_t)lyr*DD*DD;
        wf.p[4*lyr+3] = k2_w + (size_t)lyr*DD*DD;
    }
    wf.p[12] = W_logits;
    wf.p[13] = W_weight;
    wf.p[14] = fc_w;

    k_pack<<<dim3(64,15), 128>>>(wf, wfrag, (float2*)wpk);
    k_lift<<<NTOT/2, 128>>>(spikes, conv_w, conv_b, wpk, fc_b, u0);
    k_rank<<<dim3(NN/8, BB), 256>>>(coords, pskey, ppos);

    float* ucur = u0;
    float* unext = u1;
    for (int lyr = 0; lyr < 3; lyr++) {
        const float* W1 = k1_w + (size_t)lyr*258*DD;
        k_node_mma<3, true, false><<<NTOT/16, 256>>>(ucur,
            wfrag + (size_t)(4*lyr+0)*4096, wfrag + (size_t)(4*lyr+1)*4096,
            wfrag + (size_t)(4*lyr+2)*4096,
            k1_b + lyr*DD, local_b + lyr*DD,
            W1, W1 + DD, coords,
            pb, pp, pl, nullptr);
        if (lyr == 0)
            k_knn2<<<dim3(NN/128, BB), 128>>>(pskey, ppos, pix);
        k_edge_mma<<<NTOT/4, 256>>>(ucur, unext, pb, pp, pl, pix,
            wfrag + (size_t)(4*lyr+3)*4096,
            k2_b + lyr*DD, k3_w + (size_t)lyr*DD, k3_b + lyr);
        float* t = ucur; ucur = unext; unext = t;
    }

    k_node_mma<2, false, true><<<NTOT/16, 256>>>(ucur,
        wfrag + (size_t)12*4096, wfrag + (size_t)13*4096, wfrag,
        nullptr, nullptr, nullptr, nullptr, nullptr,
        nullptr, nullptr, nullptr, spl);
    k_dec_mma<<<dim3(NN/64, NN/64, BB), 256, 104448>>>(spl, out);
}